// round 1
// baseline (speedup 1.0000x reference)
#include <cuda_runtime.h>
#include <math.h>

#define N_NODESC 50000
#define N_EDGESC 800000
#define DIM 128
#define TIME_DIMC 32
#define EPSF 0.1f
#define GAMMAF 0.1f
#define INV_SQRT_D 0.08838834764831845f  // 1/sqrt(128)

// ---------------- scratch (device globals; no allocation allowed) ----------------
__device__ float g_h[N_NODESC * DIM];
__device__ float g_q[N_NODESC * DIM];
__device__ float g_k[N_NODESC * DIM];
__device__ float g_v[N_NODESC * DIM];
__device__ float g_phi[N_NODESC * DIM];
__device__ float g_e[(size_t)N_EDGESC * DIM];        // 409.6 MB
__device__ float g_te[(size_t)N_EDGESC * TIME_DIMC]; // 102.4 MB
__device__ int   g_src[N_EDGESC];
__device__ int   g_dst[N_EDGESC];
__device__ int   g_list[N_EDGESC];
__device__ int   g_deg[N_NODESC];
__device__ int   g_cur[N_NODESC];
__device__ int   g_off[N_NODESC + 1];
__device__ float g_A[DIM * DIM];          // (A^T stored k-major for gemm)
__device__ float g_wt_enc[256 * DIM];
__device__ float g_wt_e[160 * DIM];
__device__ float g_wt_q[DIM * DIM];
__device__ float g_wt_k[DIM * DIM];
__device__ float g_wt_v[DIM * DIM];
__device__ int   g_is64;

// ---------------- small utility kernels ----------------
__global__ void zero_kernel() {
    int i = blockIdx.x * blockDim.x + threadIdx.x;
    if (i < N_NODESC) { g_deg[i] = 0; g_cur[i] = 0; }
}

// Detect whether edge_index buffer is int64 or int32: indices < 50000, so for
// int64 (little-endian) every odd 32-bit word is 0. For int32 the odd words are
// real node indices (probability all 256 samples are zero ~ 0).
__global__ void detect_kernel(const int* __restrict__ ei_words) {
    __shared__ int nz;
    if (threadIdx.x == 0) nz = 0;
    __syncthreads();
    int w = ei_words[2 * threadIdx.x + 1];
    if (w != 0) atomicAdd(&nz, 1);
    __syncthreads();
    if (threadIdx.x == 0) g_is64 = (nz == 0) ? 1 : 0;
}

// Warp per edge: decode src/dst, count degree, compute time encoding row.
__global__ void pre_kernel(const void* __restrict__ ei,
                           const float* __restrict__ last_update,
                           const float* __restrict__ t,
                           const float* __restrict__ te_w,
                           const float* __restrict__ te_b) {
    int gw = (blockIdx.x * blockDim.x + threadIdx.x) >> 5;
    int lane = threadIdx.x & 31;
    if (gw >= N_EDGESC) return;
    int s = 0;
    if (lane == 0) {
        int d;
        if (g_is64) {
            const long long* p = (const long long*)ei;
            s = (int)p[gw];
            d = (int)p[N_EDGESC + gw];
        } else {
            const int* p = (const int*)ei;
            s = p[gw];
            d = p[N_EDGESC + gw];
        }
        g_src[gw] = s;
        g_dst[gw] = d;
        atomicAdd(&g_deg[d], 1);
    }
    s = __shfl_sync(0xFFFFFFFFu, s, 0);
    float rel = fabsf(last_update[s] - t[gw]);
    g_te[(size_t)gw * TIME_DIMC + lane] = cosf(rel * te_w[lane] + te_b[lane]);
}

// Single-block exclusive scan of g_deg -> g_off
__global__ void scan_kernel() {
    __shared__ int wsum[32];
    __shared__ int carry;
    int tid = threadIdx.x, lane = tid & 31, wid = tid >> 5;
    if (tid == 0) carry = 0;
    __syncthreads();
    for (int base = 0; base < N_NODESC; base += 1024) {
        int i = base + tid;
        int v = (i < N_NODESC) ? g_deg[i] : 0;
        int x = v;
#pragma unroll
        for (int o = 1; o < 32; o <<= 1) {
            int y = __shfl_up_sync(0xFFFFFFFFu, x, o);
            if (lane >= o) x += y;
        }
        if (lane == 31) wsum[wid] = x;
        __syncthreads();
        if (wid == 0) {
            int w = wsum[lane];
#pragma unroll
            for (int o = 1; o < 32; o <<= 1) {
                int y = __shfl_up_sync(0xFFFFFFFFu, w, o);
                if (lane >= o) w += y;
            }
            wsum[lane] = w;
        }
        __syncthreads();
        int prefix = carry + (wid > 0 ? wsum[wid - 1] : 0) + (x - v);
        if (i < N_NODESC) g_off[i] = prefix;
        __syncthreads();
        if (tid == 0) carry += wsum[31];
        __syncthreads();
    }
    if (threadIdx.x == 0) g_off[N_NODESC] = carry;
}

__global__ void fill_kernel() {
    int i = blockIdx.x * blockDim.x + threadIdx.x;
    if (i < N_EDGESC) {
        int d = g_dst[i];
        int pos = atomicAdd(&g_cur[d], 1);
        g_list[g_off[d] + pos] = i;
    }
}

// Wt[k*128 + j] = W[j*ldw + k]  (k-major transpose of a [128, K] weight)
__global__ void transpose_w(const float* __restrict__ W, float* __restrict__ Wt,
                            int K, int ldw) {
    int i = blockIdx.x * blockDim.x + threadIdx.x;
    if (i < DIM * K) {
        int k = i >> 7, j = i & 127;
        Wt[i] = W[j * ldw + k];
    }
}

// g_A[k*128 + j] = A[j][k] where A = Wa - Wa^T - gamma*I   (so gemm computes h@A^T)
__global__ void build_A(const float* __restrict__ Wa) {
    int i = blockIdx.x * blockDim.x + threadIdx.x;
    if (i < DIM * DIM) {
        int k = i >> 7, j = i & 127;
        float a = Wa[j * DIM + k] - Wa[k * DIM + j];
        if (j == k) a -= GAMMAF;
        g_A[i] = a;
    }
}

// ---------------- GEMM: C[M,128] = X[M,K] @ W^T (+bias / +=  / fused tanh update) ----
// Wt is k-major [K][128]. MODE 0: C = acc+bias. MODE 1: C += acc.
// MODE 2: C(=h) = h + eps*tanh(acc + phi + bias)  (in-place, row-tile safe)
#define BM 64
#define BN 128
#define BKK 16

template <int MODE>
__global__ void __launch_bounds__(256) gemm_kernel(
    const float* __restrict__ X, int ldx,
    const float* __restrict__ Wt,
    const float* __restrict__ bias,
    float* __restrict__ C,
    const float* __restrict__ phi,
    int M, int K) {
    __shared__ float  Xs[BM][BKK];          // 4 KB, row-major
    __shared__ float4 Ws[BKK][BN / 4];      // 8 KB, k-major packed by 4 cols

    int tid = threadIdx.x;
    int c = tid & 31;      // col group: cols 4c..4c+3
    int rg = tid >> 5;     // row group: rows 8rg..8rg+7
    int row0 = blockIdx.x * BM;

    float acc[8][4];
#pragma unroll
    for (int u = 0; u < 8; u++)
#pragma unroll
        for (int w = 0; w < 4; w++) acc[u][w] = 0.0f;

    for (int k0 = 0; k0 < K; k0 += BKK) {
        // load X tile (coalesced float4, conflict-free STS)
        {
            int r = tid >> 2, kq = tid & 3;
            int gr = row0 + r;
            float4 xv = make_float4(0.f, 0.f, 0.f, 0.f);
            if (gr < M) xv = *(const float4*)&X[gr * ldx + k0 + 4 * kq];
            ((float4*)&Xs[r][0])[kq] = xv;
        }
        // load W tile (coalesced float4, conflict-free STS)
#pragma unroll
        for (int it = 0; it < 2; it++) {
            int idx = tid + it * 256;
            int k = idx >> 5, c2 = idx & 31;
            Ws[k][c2] = ((const float4*)&Wt[(k0 + k) * BN])[c2];
        }
        __syncthreads();
#pragma unroll
        for (int kk = 0; kk < BKK; kk++) {
            float4 b = Ws[kk][c];
            float xv[8];
#pragma unroll
            for (int u = 0; u < 8; u++) xv[u] = Xs[8 * rg + u][kk]; // warp broadcast
#pragma unroll
            for (int u = 0; u < 8; u++) {
                acc[u][0] = fmaf(xv[u], b.x, acc[u][0]);
                acc[u][1] = fmaf(xv[u], b.y, acc[u][1]);
                acc[u][2] = fmaf(xv[u], b.z, acc[u][2]);
                acc[u][3] = fmaf(xv[u], b.w, acc[u][3]);
            }
        }
        __syncthreads();
    }

    int j0 = 4 * c;
    float4 bv = make_float4(0.f, 0.f, 0.f, 0.f);
    if (MODE != 1) bv = *(const float4*)&bias[j0];
#pragma unroll
    for (int u = 0; u < 8; u++) {
        int row = row0 + 8 * rg + u;
        if (row < M) {
            float4* cp = (float4*)&C[row * BN + j0];
            if (MODE == 0) {
                float4 o;
                o.x = acc[u][0] + bv.x; o.y = acc[u][1] + bv.y;
                o.z = acc[u][2] + bv.z; o.w = acc[u][3] + bv.w;
                *cp = o;
            } else if (MODE == 1) {
                float4 o = *cp;
                o.x += acc[u][0]; o.y += acc[u][1];
                o.z += acc[u][2]; o.w += acc[u][3];
                *cp = o;
            } else {
                float4 hv = *cp;
                float4 pv = *(const float4*)&phi[row * BN + j0];
                float4 o;
                o.x = hv.x + EPSF * tanhf(acc[u][0] + pv.x + bv.x);
                o.y = hv.y + EPSF * tanhf(acc[u][1] + pv.y + bv.y);
                o.z = hv.z + EPSF * tanhf(acc[u][2] + pv.z + bv.z);
                o.w = hv.w + EPSF * tanhf(acc[u][3] + pv.w + bv.w);
                *cp = o;
            }
        }
    }
}

// ---------------- attention + aggregation: warp per dst node, online softmax ----------
__global__ void node_pass() {
    int n = (blockIdx.x * blockDim.x + threadIdx.x) >> 5;
    int lane = threadIdx.x & 31;
    if (n >= N_NODESC) return;
    int beg = g_off[n], end = g_off[n + 1];

    float4 q = ((const float4*)&g_q[n * DIM])[lane];
    float m = -INFINITY, s = 0.0f;
    float4 acc = make_float4(0.f, 0.f, 0.f, 0.f);

    for (int i = beg; i < end; i++) {
        int eid = g_list[i];
        int sn = g_src[eid];
        float4 e4 = ((const float4*)&g_e[(size_t)eid * DIM])[lane];
        float4 kk = ((const float4*)&g_k[sn * DIM])[lane];
        float d = q.x * (kk.x + e4.x) + q.y * (kk.y + e4.y) +
                  q.z * (kk.z + e4.z) + q.w * (kk.w + e4.w);
#pragma unroll
        for (int o = 16; o; o >>= 1) d += __shfl_xor_sync(0xFFFFFFFFu, d, o);
        float l = d * INV_SQRT_D;

        float nm = fmaxf(m, l);
        float corr = __expf(m - nm);   // m = -inf on first edge -> corr = 0
        float p = __expf(l - nm);
        float4 v4 = ((const float4*)&g_v[sn * DIM])[lane];
        s = s * corr + p;
        acc.x = acc.x * corr + p * (v4.x + e4.x);
        acc.y = acc.y * corr + p * (v4.y + e4.y);
        acc.z = acc.z * corr + p * (v4.z + e4.z);
        acc.w = acc.w * corr + p * (v4.w + e4.w);
        m = nm;
    }
    float invs = (end > beg) ? 1.0f / s : 0.0f;
    float4 out = make_float4(acc.x * invs, acc.y * invs, acc.z * invs, acc.w * invs);
    ((float4*)&g_phi[n * DIM])[lane] = out;
}

// ---------------- launch ----------------
extern "C" void kernel_launch(void* const* d_in, const int* in_sizes, int n_in,
                              void* d_out, int out_size) {
    const float* x      = (const float*)d_in[0];
    const float* lu     = (const float*)d_in[1];
    const float* t      = (const float*)d_in[2];
    const float* msg    = (const float*)d_in[3];
    const void*  ei     = d_in[4];
    const float* enc_W  = (const float*)d_in[5];
    const float* enc_b  = (const float*)d_in[6];
    const float* te_w   = (const float*)d_in[7];
    const float* te_b   = (const float*)d_in[8];
    const float* Wq     = (const float*)d_in[9];
    const float* bq     = (const float*)d_in[10];
    const float* Wk     = (const float*)d_in[11];
    const float* bk     = (const float*)d_in[12];
    const float* Wv     = (const float*)d_in[13];
    const float* bv     = (const float*)d_in[14];
    const float* We     = (const float*)d_in[15];
    const float* be     = (const float*)d_in[16];
    const float* Wanti  = (const float*)d_in[17];
    const float* banti  = (const float*)d_in[18];

    float *h, *q, *k, *v, *phi, *e, *te, *A, *wt_enc, *wt_e, *wt_q, *wt_k, *wt_v;
    cudaGetSymbolAddress((void**)&h, g_h);
    cudaGetSymbolAddress((void**)&q, g_q);
    cudaGetSymbolAddress((void**)&k, g_k);
    cudaGetSymbolAddress((void**)&v, g_v);
    cudaGetSymbolAddress((void**)&phi, g_phi);
    cudaGetSymbolAddress((void**)&e, g_e);
    cudaGetSymbolAddress((void**)&te, g_te);
    cudaGetSymbolAddress((void**)&A, g_A);
    cudaGetSymbolAddress((void**)&wt_enc, g_wt_enc);
    cudaGetSymbolAddress((void**)&wt_e, g_wt_e);
    cudaGetSymbolAddress((void**)&wt_q, g_wt_q);
    cudaGetSymbolAddress((void**)&wt_k, g_wt_k);
    cudaGetSymbolAddress((void**)&wt_v, g_wt_v);

    // ---- preprocessing (per launch; deterministic) ----
    zero_kernel<<<(N_NODESC + 255) / 256, 256>>>();
    detect_kernel<<<1, 256>>>((const int*)ei);
    pre_kernel<<<N_EDGESC / 8, 256>>>(ei, lu, t, te_w, te_b);
    scan_kernel<<<1, 1024>>>();
    fill_kernel<<<(N_EDGESC + 255) / 256, 256>>>();

    transpose_w<<<(DIM * 256 + 255) / 256, 256>>>(enc_W, wt_enc, 256, 256);
    transpose_w<<<(DIM * 160 + 255) / 256, 256>>>(We, wt_e, 160, 160);
    transpose_w<<<(DIM * 128 + 255) / 256, 256>>>(Wq, wt_q, 128, 128);
    transpose_w<<<(DIM * 128 + 255) / 256, 256>>>(Wk, wt_k, 128, 128);
    transpose_w<<<(DIM * 128 + 255) / 256, 256>>>(Wv, wt_v, 128, 128);
    build_A<<<(DIM * DIM + 255) / 256, 256>>>(Wanti);

    // ---- one-time GEMMs ----
    int gb_n = (N_NODESC + BM - 1) / BM;   // 782
    int gb_e = (N_EDGESC + BM - 1) / BM;   // 12500
    gemm_kernel<0><<<gb_n, 256>>>(x, 256, wt_enc, enc_b, h, nullptr, N_NODESC, 256);
    gemm_kernel<0><<<gb_e, 256>>>(msg, 128, wt_e, be, e, nullptr, N_EDGESC, 128);
    gemm_kernel<1><<<gb_e, 256>>>(te, 32, wt_e + 128 * DIM, nullptr, e, nullptr, N_EDGESC, 32);

    // ---- 3 message-passing iterations ----
    for (int it = 0; it < 3; it++) {
        gemm_kernel<0><<<gb_n, 256>>>(h, 128, wt_q, bq, q, nullptr, N_NODESC, 128);
        gemm_kernel<0><<<gb_n, 256>>>(h, 128, wt_k, bk, k, nullptr, N_NODESC, 128);
        gemm_kernel<0><<<gb_n, 256>>>(h, 128, wt_v, bv, v, nullptr, N_NODESC, 128);
        node_pass<<<(N_NODESC + 7) / 8, 256>>>();
        gemm_kernel<2><<<gb_n, 256>>>(h, 128, A, banti, h, phi, N_NODESC, 128);
    }

    cudaMemcpyAsync(d_out, h, (size_t)N_NODESC * DIM * sizeof(float),
                    cudaMemcpyDeviceToDevice);
}

// round 3
// speedup vs baseline: 1.0681x; 1.0681x over previous
#include <cuda_runtime.h>
#include <cuda_bf16.h>
#include <math.h>
#include <stdint.h>

#define N_NODESC 50000
#define N_EDGESC 800000
#define DIM 128
#define TIME_DIMC 32
#define EPSF 0.1f
#define GAMMAF 0.1f
#define INV_SQRT_D 0.08838834764831845f  // 1/sqrt(128)

// ---------------- scratch (device globals; no allocation allowed) ----------------
__device__ float g_h[N_NODESC * DIM];
__device__ float g_q[N_NODESC * DIM];
__device__ float g_k[N_NODESC * DIM];
__device__ float g_v[N_NODESC * DIM];
__device__ float g_phi[N_NODESC * DIM];
__device__ float g_e[(size_t)N_EDGESC * DIM];        // 409.6 MB (CSR order)
__device__ float g_te[(size_t)N_EDGESC * TIME_DIMC]; // 102.4 MB
__device__ int   g_src[N_EDGESC];
__device__ int   g_dst[N_EDGESC];
__device__ int   g_srt[N_EDGESC];   // src sorted to CSR position
__device__ int   g_pos[N_EDGESC];   // edge -> CSR position
__device__ int   g_deg[N_NODESC];
__device__ int   g_cur[N_NODESC];
__device__ int   g_off[N_NODESC + 1];
__device__ int   g_is64;

// split-bf16 weight images (hi chunks then lo chunks; chunk = 16 KB = 128 rows x 128B SW128)
__device__ char g_wimg_enc[2 * 4 * 16384];
__device__ char g_wimg_e  [2 * 3 * 16384];
__device__ char g_wimg_q  [2 * 2 * 16384];
__device__ char g_wimg_k  [2 * 2 * 16384];
__device__ char g_wimg_v  [2 * 2 * 16384];
__device__ char g_wimg_a  [2 * 2 * 16384];

#define SW128(o) ((o) ^ (((o) >> 3) & 0x70))

__device__ __forceinline__ uint32_t s2u(const void* p) {
    uint32_t a;
    asm("{ .reg .u64 t; cvta.to.shared.u64 t, %1; cvt.u32.u64 %0, t; }" : "=r"(a) : "l"(p));
    return a;
}

#define LDSM4(r0, r1, r2, r3, addr)                                        \
    asm volatile("ldmatrix.sync.aligned.m8n8.x4.shared.b16 {%0,%1,%2,%3}, [%4];" \
                 : "=r"(r0), "=r"(r1), "=r"(r2), "=r"(r3) : "r"(addr))

#define MMA16816(d, a, b0, b1)                                             \
    asm volatile("mma.sync.aligned.m16n8k16.row.col.f32.bf16.bf16.f32 "    \
                 "{%0,%1,%2,%3}, {%4,%5,%6,%7}, {%8,%9}, {%0,%1,%2,%3};"   \
                 : "+f"((d)[0]), "+f"((d)[1]), "+f"((d)[2]), "+f"((d)[3])  \
                 : "r"((a)[0]), "r"((a)[1]), "r"((a)[2]), "r"((a)[3]),     \
                   "r"(b0), "r"(b1))

__device__ __forceinline__ uint32_t pack_bf16(__nv_bfloat16 a, __nv_bfloat16 b) {
    uint16_t ua = *(uint16_t*)&a, ub = *(uint16_t*)&b;
    return (uint32_t)ua | ((uint32_t)ub << 16);
}

// ---------------- small utility kernels ----------------
__global__ void zero_kernel() {
    int i = blockIdx.x * blockDim.x + threadIdx.x;
    if (i < N_NODESC) { g_deg[i] = 0; g_cur[i] = 0; }
}

__global__ void detect_kernel(const int* __restrict__ ei_words) {
    __shared__ int nz;
    if (threadIdx.x == 0) nz = 0;
    __syncthreads();
    int w = ei_words[2 * threadIdx.x + 1];
    if (w != 0) atomicAdd(&nz, 1);
    __syncthreads();
    if (threadIdx.x == 0) g_is64 = (nz == 0) ? 1 : 0;
}

// Warp per edge: decode src/dst, count degree, compute time encoding row.
__global__ void pre_kernel(const void* __restrict__ ei,
                           const float* __restrict__ last_update,
                           const float* __restrict__ t,
                           const float* __restrict__ te_w,
                           const float* __restrict__ te_b) {
    int gw = (blockIdx.x * blockDim.x + threadIdx.x) >> 5;
    int lane = threadIdx.x & 31;
    if (gw >= N_EDGESC) return;
    int s = 0;
    if (lane == 0) {
        int d;
        if (g_is64) {
            const long long* p = (const long long*)ei;
            s = (int)p[gw];
            d = (int)p[N_EDGESC + gw];
        } else {
            const int* p = (const int*)ei;
            s = p[gw];
            d = p[N_EDGESC + gw];
        }
        g_src[gw] = s;
        g_dst[gw] = d;
        atomicAdd(&g_deg[d], 1);
    }
    s = __shfl_sync(0xFFFFFFFFu, s, 0);
    float rel = fabsf(last_update[s] - t[gw]);
    g_te[(size_t)gw * TIME_DIMC + lane] = cosf(rel * te_w[lane] + te_b[lane]);
}

// Single-block exclusive scan of g_deg -> g_off
__global__ void scan_kernel() {
    __shared__ int wsum[32];
    __shared__ int carry;
    int tid = threadIdx.x, lane = tid & 31, wid = tid >> 5;
    if (tid == 0) carry = 0;
    __syncthreads();
    for (int base = 0; base < N_NODESC; base += 1024) {
        int i = base + tid;
        int v = (i < N_NODESC) ? g_deg[i] : 0;
        int x = v;
#pragma unroll
        for (int o = 1; o < 32; o <<= 1) {
            int y = __shfl_up_sync(0xFFFFFFFFu, x, o);
            if (lane >= o) x += y;
        }
        if (lane == 31) wsum[wid] = x;
        __syncthreads();
        if (wid == 0) {
            int w = wsum[lane];
#pragma unroll
            for (int o = 1; o < 32; o <<= 1) {
                int y = __shfl_up_sync(0xFFFFFFFFu, w, o);
                if (lane >= o) w += y;
            }
            wsum[lane] = w;
        }
        __syncthreads();
        int prefix = carry + (wid > 0 ? wsum[wid - 1] : 0) + (x - v);
        if (i < N_NODESC) g_off[i] = prefix;
        __syncthreads();
        if (tid == 0) carry += wsum[31];
        __syncthreads();
    }
    if (threadIdx.x == 0) g_off[N_NODESC] = carry;
}

__global__ void fill_kernel() {
    int i = blockIdx.x * blockDim.x + threadIdx.x;
    if (i < N_EDGESC) {
        int d = g_dst[i];
        int pos = g_off[d] + atomicAdd(&g_cur[d], 1);
        g_pos[i] = pos;
        g_srt[pos] = g_src[i];
    }
}

// Build split-bf16 swizzled weight image from row-major W[128, K], zero-padded to chunks*64
__global__ void build_wimg(const float* __restrict__ W, char* __restrict__ img,
                           int K, int chunks) {
    int Kpad = chunks * 64;
    int i = blockIdx.x * blockDim.x + threadIdx.x;
    if (i >= 128 * Kpad) return;
    int n = i / Kpad, k = i - n * Kpad;
    float v = (k < K) ? W[n * K + k] : 0.0f;
    __nv_bfloat16 hi = __float2bfloat16(v);
    __nv_bfloat16 lo = __float2bfloat16(v - __bfloat162float(hi));
    int chunk = k >> 6, j = k & 63;
    uint32_t off = (uint32_t)chunk * 16384u + (uint32_t)((n >> 3) * 1024) +
                   SW128((uint32_t)((n & 7) * 128 + j * 2));
    *(__nv_bfloat16*)(img + off) = hi;
    *(__nv_bfloat16*)(img + (size_t)chunks * 16384 + off) = lo;
}

// A = Wa - Wa^T - gamma*I, as B matrix rows (n = out col, k = in col)
__global__ void build_wimg_A(const float* __restrict__ Wa, char* __restrict__ img) {
    int i = blockIdx.x * blockDim.x + threadIdx.x;
    if (i >= 128 * 128) return;
    int n = i >> 7, k = i & 127;
    float v = Wa[n * 128 + k] - Wa[k * 128 + n] - ((n == k) ? GAMMAF : 0.0f);
    __nv_bfloat16 hi = __float2bfloat16(v);
    __nv_bfloat16 lo = __float2bfloat16(v - __bfloat162float(hi));
    int chunk = k >> 6, j = k & 63;
    uint32_t off = (uint32_t)chunk * 16384u + (uint32_t)((n >> 3) * 1024) +
                   SW128((uint32_t)((n & 7) * 128 + j * 2));
    *(__nv_bfloat16*)(img + off) = hi;
    *(__nv_bfloat16*)(img + 2 * 16384 + off) = lo;
}

// ---------------- mma.sync split-bf16 GEMM ----------------
// C[M,128] = X[M,Ktot] @ W^T (+bias)    MODE 0 (optional row scatter via pos)
// h = h + eps*tanh(acc + phi + bias)    MODE 2 (in-place, row-tile safe)
// X logically [X1 (K1 cols) | X2 (Ktot-K1 cols)], fp32 row-major.
// Tile: BM=64, BN=128, BK=64. 8 warps (2m x 4n), warp tile 32x32.
#define OA_HI 0
#define OA_LO 8192
#define OB_HI 16384
#define OB_LO 32768

template <int MODE>
__global__ void __launch_bounds__(256) mma_gemm(
    const float* __restrict__ X1, int ld1, int K1,
    const float* __restrict__ X2, int ld2, int Ktot,
    const char* __restrict__ Wimg, int chunks_total,
    const float* __restrict__ bias,
    float* __restrict__ C,
    const float* __restrict__ phi,
    const int* __restrict__ pos,
    int M) {
    __shared__ __align__(128) char sm[49152];
    uint32_t sb = s2u(sm);
    int tid = threadIdx.x, lane = tid & 31, wid = tid >> 5;
    int wr = wid & 1, wc = wid >> 1;
    int row0 = blockIdx.x * 64;

    float acc[2][4][4];
#pragma unroll
    for (int a = 0; a < 2; a++)
#pragma unroll
        for (int b = 0; b < 4; b++)
#pragma unroll
            for (int c = 0; c < 4; c++) acc[a][b][c] = 0.0f;

    for (int ck = 0; ck < chunks_total; ck++) {
        int k0 = ck * 64;
        if (ck) __syncthreads();

        // --- A tile: fp32 -> bf16 hi/lo, SW128 swizzled (64 rows x 64 cols) ---
        for (int i = tid; i < 64 * 32; i += 256) {
            int r = i >> 5, cp = i & 31, c = cp * 2;
            int gr = row0 + r, gc = k0 + c;
            float v0 = 0.0f, v1 = 0.0f;
            if (gr < M && gc < Ktot) {
                const float* p = (gc < K1) ? &X1[(size_t)gr * ld1 + gc]
                                           : &X2[(size_t)gr * ld2 + (gc - K1)];
                v0 = p[0]; v1 = p[1];
            }
            __nv_bfloat16 h0 = __float2bfloat16(v0), h1 = __float2bfloat16(v1);
            __nv_bfloat16 l0 = __float2bfloat16(v0 - __bfloat162float(h0));
            __nv_bfloat16 l1 = __float2bfloat16(v1 - __bfloat162float(h1));
            uint32_t off = ((uint32_t)(r >> 3) << 10) +
                           SW128((uint32_t)(((r & 7) << 7) + c * 2));
            *(uint32_t*)(sm + OA_HI + off) = pack_bf16(h0, h1);
            *(uint32_t*)(sm + OA_LO + off) = pack_bf16(l0, l1);
        }
        // --- B tile: copy prebuilt 16KB chunk (hi + lo) ---
        {
            const float4* shi = (const float4*)(Wimg + (size_t)ck * 16384);
            const float4* slo = (const float4*)(Wimg + ((size_t)chunks_total + ck) * 16384);
            float4* dhi = (float4*)(sm + OB_HI);
            float4* dlo = (float4*)(sm + OB_LO);
#pragma unroll
            for (int i = tid; i < 1024; i += 256) { dhi[i] = shi[i]; dlo[i] = slo[i]; }
        }
        __syncthreads();

        // --- compute: 4 k16 steps per chunk, 3 split-precision passes ---
#pragma unroll
        for (int kt = 0; kt < 4; kt++) {
            uint32_t ah[2][4], al[2][4], bh[2][4], bl[2][4];
#pragma unroll
            for (int mt = 0; mt < 2; mt++) {
                int r = wr * 32 + mt * 16 + (lane & 15);
                uint32_t off = ((uint32_t)(r >> 3) << 10) +
                               SW128((uint32_t)(((r & 7) << 7) + kt * 32 + ((lane >> 4) << 4)));
                LDSM4(ah[mt][0], ah[mt][1], ah[mt][2], ah[mt][3], sb + OA_HI + off);
                LDSM4(al[mt][0], al[mt][1], al[mt][2], al[mt][3], sb + OA_LO + off);
            }
#pragma unroll
            for (int np = 0; np < 2; np++) {
                int n = wc * 32 + np * 16 + (lane & 7) + ((lane >> 4) << 3);
                uint32_t off = ((uint32_t)(n >> 3) << 10) +
                               SW128((uint32_t)(((n & 7) << 7) + kt * 32 + (((lane >> 3) & 1) << 4)));
                LDSM4(bh[np][0], bh[np][1], bh[np][2], bh[np][3], sb + OB_HI + off);
                LDSM4(bl[np][0], bl[np][1], bl[np][2], bl[np][3], sb + OB_LO + off);
            }
#pragma unroll
            for (int mt = 0; mt < 2; mt++)
#pragma unroll
                for (int nt = 0; nt < 4; nt++) {
                    uint32_t* ph = &bh[nt >> 1][(nt & 1) * 2];
                    uint32_t* pl = &bl[nt >> 1][(nt & 1) * 2];
                    MMA16816(acc[mt][nt], ah[mt], ph[0], ph[1]);  // hi*hi
                    MMA16816(acc[mt][nt], al[mt], ph[0], ph[1]);  // lo*hi
                    MMA16816(acc[mt][nt], ah[mt], pl[0], pl[1]);  // hi*lo
                }
        }
    }

    // --- epilogue ---
#pragma unroll
    for (int mt = 0; mt < 2; mt++) {
        int rbase = row0 + wr * 32 + mt * 16 + (lane >> 2);
#pragma unroll
        for (int half = 0; half < 2; half++) {
            int row = rbase + half * 8;
            if (row < M) {
                int orow = pos ? pos[row] : row;
#pragma unroll
                for (int nt = 0; nt < 4; nt++) {
                    int col = wc * 32 + nt * 8 + (lane & 3) * 2;
                    float a0 = acc[mt][nt][half * 2 + 0];
                    float a1 = acc[mt][nt][half * 2 + 1];
                    float b0 = __ldg(&bias[col]), b1 = __ldg(&bias[col + 1]);
                    float2* cp2 = (float2*)&C[(size_t)orow * 128 + col];
                    if (MODE == 0) {
                        float2 o; o.x = a0 + b0; o.y = a1 + b1;
                        *cp2 = o;
                    } else {
                        float2 hv = *cp2;
                        float2 pv = *(const float2*)&phi[(size_t)orow * 128 + col];
                        float2 o;
                        o.x = hv.x + EPSF * tanhf(a0 + pv.x + b0);
                        o.y = hv.y + EPSF * tanhf(a1 + pv.y + b1);
                        *cp2 = o;
                    }
                }
            }
        }
    }
}

// ---------------- attention + aggregation: warp per dst node, online softmax ----------
__global__ void node_pass() {
    int n = (blockIdx.x * blockDim.x + threadIdx.x) >> 5;
    int lane = threadIdx.x & 31;
    if (n >= N_NODESC) return;
    int beg = g_off[n], end = g_off[n + 1];

    float4 q = ((const float4*)&g_q[n * DIM])[lane];
    float m = -INFINITY, s = 0.0f;
    float4 acc = make_float4(0.f, 0.f, 0.f, 0.f);

    for (int i = beg; i < end; i++) {
        int sn = g_srt[i];
        float4 e4 = ((const float4*)&g_e[(size_t)i * DIM])[lane];
        float4 kk = ((const float4*)&g_k[sn * DIM])[lane];
        float d = q.x * (kk.x + e4.x) + q.y * (kk.y + e4.y) +
                  q.z * (kk.z + e4.z) + q.w * (kk.w + e4.w);
#pragma unroll
        for (int o = 16; o; o >>= 1) d += __shfl_xor_sync(0xFFFFFFFFu, d, o);
        float l = d * INV_SQRT_D;

        float nm = fmaxf(m, l);
        float corr = __expf(m - nm);
        float p = __expf(l - nm);
        float4 v4 = ((const float4*)&g_v[sn * DIM])[lane];
        s = s * corr + p;
        acc.x = acc.x * corr + p * (v4.x + e4.x);
        acc.y = acc.y * corr + p * (v4.y + e4.y);
        acc.z = acc.z * corr + p * (v4.z + e4.z);
        acc.w = acc.w * corr + p * (v4.w + e4.w);
        m = nm;
    }
    float invs = (end > beg) ? 1.0f / s : 0.0f;
    float4 out = make_float4(acc.x * invs, acc.y * invs, acc.z * invs, acc.w * invs);
    ((float4*)&g_phi[n * DIM])[lane] = out;
}

// ---------------- launch ----------------
extern "C" void kernel_launch(void* const* d_in, const int* in_sizes, int n_in,
                              void* d_out, int out_size) {
    const float* x      = (const float*)d_in[0];
    const float* lu     = (const float*)d_in[1];
    const float* t      = (const float*)d_in[2];
    const float* msg    = (const float*)d_in[3];
    const void*  ei     = d_in[4];
    const float* enc_W  = (const float*)d_in[5];
    const float* enc_b  = (const float*)d_in[6];
    const float* te_w   = (const float*)d_in[7];
    const float* te_b   = (const float*)d_in[8];
    const float* Wq     = (const float*)d_in[9];
    const float* bq     = (const float*)d_in[10];
    const float* Wk     = (const float*)d_in[11];
    const float* bk     = (const float*)d_in[12];
    const float* Wv     = (const float*)d_in[13];
    const float* bv     = (const float*)d_in[14];
    const float* We     = (const float*)d_in[15];
    const float* be     = (const float*)d_in[16];
    const float* Wanti  = (const float*)d_in[17];
    const float* banti  = (const float*)d_in[18];

    float *h, *q, *k, *v, *phi, *e, *te;
    int *pos;
    char *wimg_enc, *wimg_e, *wimg_q, *wimg_k, *wimg_v, *wimg_a;
    cudaGetSymbolAddress((void**)&h, g_h);
    cudaGetSymbolAddress((void**)&q, g_q);
    cudaGetSymbolAddress((void**)&k, g_k);
    cudaGetSymbolAddress((void**)&v, g_v);
    cudaGetSymbolAddress((void**)&phi, g_phi);
    cudaGetSymbolAddress((void**)&e, g_e);
    cudaGetSymbolAddress((void**)&te, g_te);
    cudaGetSymbolAddress((void**)&pos, g_pos);
    cudaGetSymbolAddress((void**)&wimg_enc, g_wimg_enc);
    cudaGetSymbolAddress((void**)&wimg_e, g_wimg_e);
    cudaGetSymbolAddress((void**)&wimg_q, g_wimg_q);
    cudaGetSymbolAddress((void**)&wimg_k, g_wimg_k);
    cudaGetSymbolAddress((void**)&wimg_v, g_wimg_v);
    cudaGetSymbolAddress((void**)&wimg_a, g_wimg_a);

    // ---- preprocessing ----
    zero_kernel<<<(N_NODESC + 255) / 256, 256>>>();
    detect_kernel<<<1, 256>>>((const int*)ei);
    pre_kernel<<<N_EDGESC / 8, 256>>>(ei, lu, t, te_w, te_b);
    scan_kernel<<<1, 1024>>>();
    fill_kernel<<<(N_EDGESC + 255) / 256, 256>>>();

    build_wimg<<<(128 * 4 * 64 + 255) / 256, 256>>>(enc_W, wimg_enc, 256, 4);
    build_wimg<<<(128 * 3 * 64 + 255) / 256, 256>>>(We, wimg_e, 160, 3);
    build_wimg<<<(128 * 2 * 64 + 255) / 256, 256>>>(Wq, wimg_q, 128, 2);
    build_wimg<<<(128 * 2 * 64 + 255) / 256, 256>>>(Wk, wimg_k, 128, 2);
    build_wimg<<<(128 * 2 * 64 + 255) / 256, 256>>>(Wv, wimg_v, 128, 2);
    build_wimg_A<<<(128 * 128 + 255) / 256, 256>>>(Wanti, wimg_a);

    // ---- one-time GEMMs ----
    int gb_n = (N_NODESC + 63) / 64;   // 782
    int gb_e = N_EDGESC / 64;          // 12500
    mma_gemm<0><<<gb_n, 256>>>(x, 256, 256, nullptr, 0, 256,
                               wimg_enc, 4, enc_b, h, nullptr, nullptr, N_NODESC);
    mma_gemm<0><<<gb_e, 256>>>(msg, 128, 128, te, 32, 160,
                               wimg_e, 3, be, e, nullptr, pos, N_EDGESC);

    // ---- 3 message-passing iterations ----
    for (int it = 0; it < 3; it++) {
        mma_gemm<0><<<gb_n, 256>>>(h, 128, 128, nullptr, 0, 128,
                                   wimg_q, 2, bq, q, nullptr, nullptr, N_NODESC);
        mma_gemm<0><<<gb_n, 256>>>(h, 128, 128, nullptr, 0, 128,
                                   wimg_k, 2, bk, k, nullptr, nullptr, N_NODESC);
        mma_gemm<0><<<gb_n, 256>>>(h, 128, 128, nullptr, 0, 128,
                                   wimg_v, 2, bv, v, nullptr, nullptr, N_NODESC);
        node_pass<<<(N_NODESC + 7) / 8, 256>>>();
        mma_gemm<2><<<gb_n, 256>>>(h, 128, 128, nullptr, 0, 128,
                                   wimg_a, 2, banti, h, phi, nullptr, N_NODESC);
    }

    cudaMemcpyAsync(d_out, h, (size_t)N_NODESC * DIM * sizeof(float),
                    cudaMemcpyDeviceToDevice);
}

// round 4
// speedup vs baseline: 1.2197x; 1.1419x over previous
#include <cuda_runtime.h>
#include <cuda_bf16.h>
#include <cuda_fp16.h>
#include <math.h>
#include <stdint.h>

#define N_NODESC 50000
#define N_EDGESC 800000
#define DIM 128
#define TIME_DIMC 32
#define EPSF 0.1f
#define GAMMAF 0.1f
#define INV_SQRT_D 0.08838834764831845f  // 1/sqrt(128)

// ---------------- scratch (device globals; no allocation allowed) ----------------
__device__ float  g_h[N_NODESC * DIM];
__device__ float  g_phi[N_NODESC * DIM];
__device__ __half g_qh[N_NODESC * DIM];
__device__ __half g_kh[N_NODESC * DIM];
__device__ __half g_vh[N_NODESC * DIM];
__device__ __half g_eh[(size_t)N_EDGESC * DIM];      // 204.8 MB (CSR order)
__device__ float  g_te[(size_t)N_EDGESC * TIME_DIMC];
__device__ int    g_src[N_EDGESC];
__device__ int    g_dst[N_EDGESC];
__device__ int    g_srt[N_EDGESC];   // src sorted to CSR position
__device__ int    g_pos[N_EDGESC];   // edge -> CSR position
__device__ int    g_deg[N_NODESC];
__device__ int    g_cur[N_NODESC];
__device__ int    g_off[N_NODESC + 1];
__device__ int    g_bsum[64];
__device__ int    g_is64;

// split-bf16 weight images (hi chunks then lo chunks; chunk = 16 KB = 128 rows x 128B SW128)
__device__ char g_wimg_enc[2 * 4 * 16384];
__device__ char g_wimg_e  [2 * 3 * 16384];
__device__ char g_wimg_qkv[3 * 2 * 2 * 16384];   // q, k, v images back to back (65536 each)
__device__ char g_wimg_a  [2 * 2 * 16384];

#define SW128(o) ((o) ^ (((o) >> 3) & 0x70))

__device__ __forceinline__ uint32_t s2u(const void* p) {
    uint32_t a;
    asm("{ .reg .u64 t; cvta.to.shared.u64 t, %1; cvt.u32.u64 %0, t; }" : "=r"(a) : "l"(p));
    return a;
}

#define LDSM4(r0, r1, r2, r3, addr)                                        \
    asm volatile("ldmatrix.sync.aligned.m8n8.x4.shared.b16 {%0,%1,%2,%3}, [%4];" \
                 : "=r"(r0), "=r"(r1), "=r"(r2), "=r"(r3) : "r"(addr))

#define MMA16816(d, a, b0, b1)                                             \
    asm volatile("mma.sync.aligned.m16n8k16.row.col.f32.bf16.bf16.f32 "    \
                 "{%0,%1,%2,%3}, {%4,%5,%6,%7}, {%8,%9}, {%0,%1,%2,%3};"   \
                 : "+f"((d)[0]), "+f"((d)[1]), "+f"((d)[2]), "+f"((d)[3])  \
                 : "r"((a)[0]), "r"((a)[1]), "r"((a)[2]), "r"((a)[3]),     \
                   "r"(b0), "r"(b1))

__device__ __forceinline__ uint32_t pack_bf16(__nv_bfloat16 a, __nv_bfloat16 b) {
    uint16_t ua = *(uint16_t*)&a, ub = *(uint16_t*)&b;
    return (uint32_t)ua | ((uint32_t)ub << 16);
}
__device__ __forceinline__ float4 h2f4(uint2 w) {
    __half2 a = *(__half2*)&w.x, b = *(__half2*)&w.y;
    float2 fa = __half22float2(a), fb = __half22float2(b);
    return make_float4(fa.x, fa.y, fb.x, fb.y);
}

// ---------------- small utility kernels ----------------
__global__ void zero_kernel() {
    int i = blockIdx.x * blockDim.x + threadIdx.x;
    if (i < N_NODESC) { g_deg[i] = 0; g_cur[i] = 0; }
}

__global__ void detect_kernel(const int* __restrict__ ei_words) {
    __shared__ int nz;
    if (threadIdx.x == 0) nz = 0;
    __syncthreads();
    int w = ei_words[2 * threadIdx.x + 1];
    if (w != 0) atomicAdd(&nz, 1);
    __syncthreads();
    if (threadIdx.x == 0) g_is64 = (nz == 0) ? 1 : 0;
}

// Warp per edge: decode src/dst, count degree, compute time encoding row.
__global__ void pre_kernel(const void* __restrict__ ei,
                           const float* __restrict__ last_update,
                           const float* __restrict__ t,
                           const float* __restrict__ te_w,
                           const float* __restrict__ te_b) {
    int gw = (blockIdx.x * blockDim.x + threadIdx.x) >> 5;
    int lane = threadIdx.x & 31;
    if (gw >= N_EDGESC) return;
    int s = 0;
    if (lane == 0) {
        int d;
        if (g_is64) {
            const long long* p = (const long long*)ei;
            s = (int)p[gw];
            d = (int)p[N_EDGESC + gw];
        } else {
            const int* p = (const int*)ei;
            s = p[gw];
            d = p[N_EDGESC + gw];
        }
        g_src[gw] = s;
        g_dst[gw] = d;
        atomicAdd(&g_deg[d], 1);
    }
    s = __shfl_sync(0xFFFFFFFFu, s, 0);
    float rel = fabsf(last_update[s] - t[gw]);
    g_te[(size_t)gw * TIME_DIMC + lane] = cosf(rel * te_w[lane] + te_b[lane]);
}

// ---- 3-kernel scan of g_deg -> g_off ----
__global__ void scan1() {
    __shared__ int ws[32];
    int tid = threadIdx.x, lane = tid & 31, wid = tid >> 5;
    int i = blockIdx.x * 1024 + tid;
    int v = (i < N_NODESC) ? g_deg[i] : 0;
    int x = v;
#pragma unroll
    for (int o = 1; o < 32; o <<= 1) {
        int y = __shfl_up_sync(0xFFFFFFFFu, x, o);
        if (lane >= o) x += y;
    }
    if (lane == 31) ws[wid] = x;
    __syncthreads();
    if (wid == 0) {
        int w = ws[lane];
#pragma unroll
        for (int o = 1; o < 32; o <<= 1) {
            int y = __shfl_up_sync(0xFFFFFFFFu, w, o);
            if (lane >= o) w += y;
        }
        ws[lane] = w;
    }
    __syncthreads();
    int excl = x - v + (wid ? ws[wid - 1] : 0);
    if (i < N_NODESC) g_off[i] = excl;
    if (tid == 1023) g_bsum[blockIdx.x] = ws[31];
}
__global__ void scan2(int nb) {
    if (threadIdx.x == 0) {
        int run = 0;
        for (int b = 0; b < nb; b++) { int t = g_bsum[b]; g_bsum[b] = run; run += t; }
        g_off[N_NODESC] = run;
    }
}
__global__ void scan3() {
    int i = blockIdx.x * 1024 + threadIdx.x;
    if (i < N_NODESC) g_off[i] += g_bsum[blockIdx.x];
}

__global__ void fill_kernel() {
    int i = blockIdx.x * blockDim.x + threadIdx.x;
    if (i < N_EDGESC) {
        int d = g_dst[i];
        int pos = g_off[d] + atomicAdd(&g_cur[d], 1);
        g_pos[i] = pos;
        g_srt[pos] = g_src[i];
    }
}

// Build split-bf16 swizzled weight image from row-major W[128, K], zero-padded to chunks*64
__global__ void build_wimg(const float* __restrict__ W, char* __restrict__ img,
                           int K, int chunks) {
    int Kpad = chunks * 64;
    int i = blockIdx.x * blockDim.x + threadIdx.x;
    if (i >= 128 * Kpad) return;
    int n = i / Kpad, k = i - n * Kpad;
    float v = (k < K) ? W[n * K + k] : 0.0f;
    __nv_bfloat16 hi = __float2bfloat16(v);
    __nv_bfloat16 lo = __float2bfloat16(v - __bfloat162float(hi));
    int chunk = k >> 6, j = k & 63;
    uint32_t off = (uint32_t)chunk * 16384u + (uint32_t)((n >> 3) * 1024) +
                   SW128((uint32_t)((n & 7) * 128 + j * 2));
    *(__nv_bfloat16*)(img + off) = hi;
    *(__nv_bfloat16*)(img + (size_t)chunks * 16384 + off) = lo;
}

// A = Wa - Wa^T - gamma*I, as B matrix rows (n = out col, k = in col)
__global__ void build_wimg_A(const float* __restrict__ Wa, char* __restrict__ img) {
    int i = blockIdx.x * blockDim.x + threadIdx.x;
    if (i >= 128 * 128) return;
    int n = i >> 7, k = i & 127;
    float v = Wa[n * 128 + k] - Wa[k * 128 + n] - ((n == k) ? GAMMAF : 0.0f);
    __nv_bfloat16 hi = __float2bfloat16(v);
    __nv_bfloat16 lo = __float2bfloat16(v - __bfloat162float(hi));
    int chunk = k >> 6, j = k & 63;
    uint32_t off = (uint32_t)chunk * 16384u + (uint32_t)((n >> 3) * 1024) +
                   SW128((uint32_t)((n & 7) * 128 + j * 2));
    *(__nv_bfloat16*)(img + off) = hi;
    *(__nv_bfloat16*)(img + 2 * 16384 + off) = lo;
}

// ---------------- mma.sync split-bf16 GEMM ----------------
// MODE 0: C(f32)[M,128] = X@W^T + bias
// MODE 1: C(f16)[M,128] = X@W^T + bias, optional row scatter via pos, smem-staged rows
// MODE 2: h = h + eps*tanh(acc + phi + bias)  in-place fp32
// Tile: BM=64, BN=128, BK=64. 8 warps (2m x 4n), warp tile 32x32.
#define OA_HI 0
#define OA_LO 8192
#define OB_HI 16384
#define OB_LO 32768

template <int MODE>
__global__ void __launch_bounds__(256) mma_gemm(
    const float* __restrict__ X1, int ld1, int K1,
    const float* __restrict__ X2, int ld2, int Ktot,
    const char* __restrict__ Wimg, int chunks_total,
    const float* __restrict__ bias,
    void* __restrict__ Cout,
    const float* __restrict__ phi,
    const int* __restrict__ pos,
    int M) {
    __shared__ __align__(128) char sm[49152];
    uint32_t sb = s2u(sm);
    int tid = threadIdx.x, lane = tid & 31, wid = tid >> 5;
    int wr = wid & 1, wc = wid >> 1;
    int row0 = blockIdx.x * 64;

    float acc[2][4][4];
#pragma unroll
    for (int a = 0; a < 2; a++)
#pragma unroll
        for (int b = 0; b < 4; b++)
#pragma unroll
            for (int c = 0; c < 4; c++) acc[a][b][c] = 0.0f;

    for (int ck = 0; ck < chunks_total; ck++) {
        int k0 = ck * 64;
        if (ck) __syncthreads();

        // --- A tile: fp32 -> bf16 hi/lo, SW128 swizzled (64 rows x 64 cols) ---
        for (int i = tid; i < 64 * 32; i += 256) {
            int r = i >> 5, cp = i & 31, c = cp * 2;
            int gr = row0 + r, gc = k0 + c;
            float v0 = 0.0f, v1 = 0.0f;
            if (gr < M && gc < Ktot) {
                const float* p = (gc < K1) ? &X1[(size_t)gr * ld1 + gc]
                                           : &X2[(size_t)gr * ld2 + (gc - K1)];
                v0 = p[0]; v1 = p[1];
            }
            __nv_bfloat16 h0 = __float2bfloat16(v0), h1 = __float2bfloat16(v1);
            __nv_bfloat16 l0 = __float2bfloat16(v0 - __bfloat162float(h0));
            __nv_bfloat16 l1 = __float2bfloat16(v1 - __bfloat162float(h1));
            uint32_t off = ((uint32_t)(r >> 3) << 10) +
                           SW128((uint32_t)(((r & 7) << 7) + c * 2));
            *(uint32_t*)(sm + OA_HI + off) = pack_bf16(h0, h1);
            *(uint32_t*)(sm + OA_LO + off) = pack_bf16(l0, l1);
        }
        // --- B tile: copy prebuilt 16KB chunk (hi + lo) ---
        {
            const float4* shi = (const float4*)(Wimg + (size_t)ck * 16384);
            const float4* slo = (const float4*)(Wimg + ((size_t)chunks_total + ck) * 16384);
            float4* dhi = (float4*)(sm + OB_HI);
            float4* dlo = (float4*)(sm + OB_LO);
#pragma unroll
            for (int i = tid; i < 1024; i += 256) { dhi[i] = shi[i]; dlo[i] = slo[i]; }
        }
        __syncthreads();

#pragma unroll
        for (int kt = 0; kt < 4; kt++) {
            uint32_t ah[2][4], al[2][4], bh[2][4], bl[2][4];
#pragma unroll
            for (int mt = 0; mt < 2; mt++) {
                int r = wr * 32 + mt * 16 + (lane & 15);
                uint32_t off = ((uint32_t)(r >> 3) << 10) +
                               SW128((uint32_t)(((r & 7) << 7) + kt * 32 + ((lane >> 4) << 4)));
                LDSM4(ah[mt][0], ah[mt][1], ah[mt][2], ah[mt][3], sb + OA_HI + off);
                LDSM4(al[mt][0], al[mt][1], al[mt][2], al[mt][3], sb + OA_LO + off);
            }
#pragma unroll
            for (int np = 0; np < 2; np++) {
                int n = wc * 32 + np * 16 + (lane & 7) + ((lane >> 4) << 3);
                uint32_t off = ((uint32_t)(n >> 3) << 10) +
                               SW128((uint32_t)(((n & 7) << 7) + kt * 32 + (((lane >> 3) & 1) << 4)));
                LDSM4(bh[np][0], bh[np][1], bh[np][2], bh[np][3], sb + OB_HI + off);
                LDSM4(bl[np][0], bl[np][1], bl[np][2], bl[np][3], sb + OB_LO + off);
            }
#pragma unroll
            for (int mt = 0; mt < 2; mt++)
#pragma unroll
                for (int nt = 0; nt < 4; nt++) {
                    uint32_t* ph = &bh[nt >> 1][(nt & 1) * 2];
                    uint32_t* pl = &bl[nt >> 1][(nt & 1) * 2];
                    MMA16816(acc[mt][nt], ah[mt], ph[0], ph[1]);
                    MMA16816(acc[mt][nt], al[mt], ph[0], ph[1]);
                    MMA16816(acc[mt][nt], ah[mt], pl[0], pl[1]);
                }
        }
    }

    if (MODE == 1) {
        // stage half rows in smem, then contiguous 256B row writes (with scatter)
        __half* Ch = (__half*)Cout;
        __syncthreads();
#pragma unroll
        for (int mt = 0; mt < 2; mt++)
#pragma unroll
            for (int half_ = 0; half_ < 2; half_++) {
                int rl = wr * 32 + mt * 16 + (lane >> 2) + half_ * 8;
#pragma unroll
                for (int nt = 0; nt < 4; nt++) {
                    int col = wc * 32 + nt * 8 + (lane & 3) * 2;
                    float a0 = acc[mt][nt][half_ * 2 + 0] + __ldg(&bias[col]);
                    float a1 = acc[mt][nt][half_ * 2 + 1] + __ldg(&bias[col + 1]);
                    *(__half2*)(sm + rl * 256 + col * 2) = __floats2half2_rn(a0, a1);
                }
            }
        __syncthreads();
        int r = tid >> 2, part = tid & 3;
        int grow = row0 + r;
        if (grow < M) {
            int orow = pos ? pos[grow] : grow;
            const uint4* sp = (const uint4*)(sm + r * 256 + part * 64);
            uint4* dp = (uint4*)((char*)(Ch + (size_t)orow * 128) + part * 64);
#pragma unroll
            for (int u = 0; u < 4; u++) dp[u] = sp[u];
        }
        return;
    }

    float* C = (float*)Cout;
#pragma unroll
    for (int mt = 0; mt < 2; mt++) {
        int rbase = row0 + wr * 32 + mt * 16 + (lane >> 2);
#pragma unroll
        for (int half_ = 0; half_ < 2; half_++) {
            int row = rbase + half_ * 8;
            if (row < M) {
#pragma unroll
                for (int nt = 0; nt < 4; nt++) {
                    int col = wc * 32 + nt * 8 + (lane & 3) * 2;
                    float a0 = acc[mt][nt][half_ * 2 + 0];
                    float a1 = acc[mt][nt][half_ * 2 + 1];
                    float b0 = __ldg(&bias[col]), b1 = __ldg(&bias[col + 1]);
                    float2* cp2 = (float2*)&C[(size_t)row * 128 + col];
                    if (MODE == 0) {
                        float2 o; o.x = a0 + b0; o.y = a1 + b1;
                        *cp2 = o;
                    } else {
                        float2 hv = *cp2;
                        float2 pv = *(const float2*)&phi[(size_t)row * 128 + col];
                        float2 o;
                        o.x = hv.x + EPSF * tanhf(a0 + pv.x + b0);
                        o.y = hv.y + EPSF * tanhf(a1 + pv.y + b1);
                        *cp2 = o;
                    }
                }
            }
        }
    }
}

// ---------------- fused q/k/v GEMM: A (h tile) converted once, 3 B matrices ----------------
// dynamic smem 64KB: A[ck] hi at ck*16384, lo at ck*16384+8192; B hi 32768, lo 49152.
__global__ void __launch_bounds__(256) qkv_gemm(
    const float* __restrict__ X,
    const char* __restrict__ Wimg3,
    const float* __restrict__ b_q, const float* __restrict__ b_k, const float* __restrict__ b_v,
    __half* __restrict__ Q, __half* __restrict__ K, __half* __restrict__ V,
    int M) {
    extern __shared__ __align__(128) char sm[];
    uint32_t sb = s2u(sm);
    int tid = threadIdx.x, lane = tid & 31, wid = tid >> 5;
    int wr = wid & 1, wc = wid >> 1;
    int row0 = blockIdx.x * 64;

    // A conversion (both K chunks, once)
#pragma unroll
    for (int ck = 0; ck < 2; ck++) {
        for (int i = tid; i < 64 * 32; i += 256) {
            int r = i >> 5, cp = i & 31, c = cp * 2;
            int gr = row0 + r, gc = ck * 64 + c;
            float v0 = 0.0f, v1 = 0.0f;
            if (gr < M) {
                const float* p = &X[(size_t)gr * 128 + gc];
                v0 = p[0]; v1 = p[1];
            }
            __nv_bfloat16 h0 = __float2bfloat16(v0), h1 = __float2bfloat16(v1);
            __nv_bfloat16 l0 = __float2bfloat16(v0 - __bfloat162float(h0));
            __nv_bfloat16 l1 = __float2bfloat16(v1 - __bfloat162float(h1));
            uint32_t off = (uint32_t)ck * 16384u + ((uint32_t)(r >> 3) << 10) +
                           SW128((uint32_t)(((r & 7) << 7) + c * 2));
            *(uint32_t*)(sm + off) = pack_bf16(h0, h1);
            *(uint32_t*)(sm + 8192 + off) = pack_bf16(l0, l1);
        }
    }

    const float* biases[3] = {b_q, b_k, b_v};
    __half* outs[3] = {Q, K, V};

    for (int out = 0; out < 3; out++) {
        float acc[2][4][4];
#pragma unroll
        for (int a = 0; a < 2; a++)
#pragma unroll
            for (int b = 0; b < 4; b++)
#pragma unroll
                for (int c = 0; c < 4; c++) acc[a][b][c] = 0.0f;

#pragma unroll
        for (int ck = 0; ck < 2; ck++) {
            __syncthreads();  // protects B region + staging reuse
            {
                const float4* shi = (const float4*)(Wimg3 + (size_t)out * 65536 + (size_t)ck * 16384);
                const float4* slo = (const float4*)(Wimg3 + (size_t)out * 65536 + 32768 + (size_t)ck * 16384);
                float4* dhi = (float4*)(sm + 32768);
                float4* dlo = (float4*)(sm + 49152);
#pragma unroll
                for (int i = tid; i < 1024; i += 256) { dhi[i] = shi[i]; dlo[i] = slo[i]; }
            }
            __syncthreads();

#pragma unroll
            for (int kt = 0; kt < 4; kt++) {
                uint32_t ah[2][4], al[2][4], bh[2][4], bl[2][4];
#pragma unroll
                for (int mt = 0; mt < 2; mt++) {
                    int r = wr * 32 + mt * 16 + (lane & 15);
                    uint32_t off = (uint32_t)ck * 16384u + ((uint32_t)(r >> 3) << 10) +
                                   SW128((uint32_t)(((r & 7) << 7) + kt * 32 + ((lane >> 4) << 4)));
                    LDSM4(ah[mt][0], ah[mt][1], ah[mt][2], ah[mt][3], sb + off);
                    LDSM4(al[mt][0], al[mt][1], al[mt][2], al[mt][3], sb + 8192 + off);
                }
#pragma unroll
                for (int np = 0; np < 2; np++) {
                    int n = wc * 32 + np * 16 + (lane & 7) + ((lane >> 4) << 3);
                    uint32_t off = ((uint32_t)(n >> 3) << 10) +
                                   SW128((uint32_t)(((n & 7) << 7) + kt * 32 + (((lane >> 3) & 1) << 4)));
                    LDSM4(bh[np][0], bh[np][1], bh[np][2], bh[np][3], sb + 32768 + off);
                    LDSM4(bl[np][0], bl[np][1], bl[np][2], bl[np][3], sb + 49152 + off);
                }
#pragma unroll
                for (int mt = 0; mt < 2; mt++)
#pragma unroll
                    for (int nt = 0; nt < 4; nt++) {
                        uint32_t* ph = &bh[nt >> 1][(nt & 1) * 2];
                        uint32_t* pl = &bl[nt >> 1][(nt & 1) * 2];
                        MMA16816(acc[mt][nt], ah[mt], ph[0], ph[1]);
                        MMA16816(acc[mt][nt], al[mt], ph[0], ph[1]);
                        MMA16816(acc[mt][nt], ah[mt], pl[0], pl[1]);
                    }
            }
        }

        // staged half epilogue into B-hi region
        const float* bias = biases[out];
        __syncthreads();
#pragma unroll
        for (int mt = 0; mt < 2; mt++)
#pragma unroll
            for (int half_ = 0; half_ < 2; half_++) {
                int rl = wr * 32 + mt * 16 + (lane >> 2) + half_ * 8;
#pragma unroll
                for (int nt = 0; nt < 4; nt++) {
                    int col = wc * 32 + nt * 8 + (lane & 3) * 2;
                    float a0 = acc[mt][nt][half_ * 2 + 0] + __ldg(&bias[col]);
                    float a1 = acc[mt][nt][half_ * 2 + 1] + __ldg(&bias[col + 1]);
                    *(__half2*)(sm + 32768 + rl * 256 + col * 2) = __floats2half2_rn(a0, a1);
                }
            }
        __syncthreads();
        {
            int r = tid >> 2, part = tid & 3;
            int grow = row0 + r;
            if (grow < M) {
                const uint4* sp = (const uint4*)(sm + 32768 + r * 256 + part * 64);
                uint4* dp = (uint4*)((char*)(outs[out] + (size_t)grow * 128) + part * 64);
#pragma unroll
                for (int u = 0; u < 4; u++) dp[u] = sp[u];
            }
        }
    }
}

// ---------------- attention + aggregation: warp/node, 2-chain online softmax ----------
__global__ void node_pass() {
    int n = (blockIdx.x * blockDim.x + threadIdx.x) >> 5;
    int lane = threadIdx.x & 31;
    if (n >= N_NODESC) return;
    int beg = g_off[n], end = g_off[n + 1];
    if (beg == end) {
        ((float4*)&g_phi[(size_t)n * DIM])[lane] = make_float4(0.f, 0.f, 0.f, 0.f);
        return;
    }

    float4 q = h2f4(*(const uint2*)(g_qh + (size_t)n * DIM + lane * 4));

    float mA = -INFINITY, sA = 0.0f, mB = -INFINITY, sB = 0.0f;
    float4 aA = make_float4(0.f, 0.f, 0.f, 0.f);
    float4 aB = make_float4(0.f, 0.f, 0.f, 0.f);

    int i = beg;
    for (; i + 1 < end; i += 2) {
        int s0 = g_srt[i], s1 = g_srt[i + 1];
        uint2 e0w = *(const uint2*)(g_eh + (size_t)i * DIM + lane * 4);
        uint2 e1w = *(const uint2*)(g_eh + (size_t)(i + 1) * DIM + lane * 4);
        uint2 k0w = *(const uint2*)(g_kh + (size_t)s0 * DIM + lane * 4);
        uint2 k1w = *(const uint2*)(g_kh + (size_t)s1 * DIM + lane * 4);
        uint2 v0w = *(const uint2*)(g_vh + (size_t)s0 * DIM + lane * 4);
        uint2 v1w = *(const uint2*)(g_vh + (size_t)s1 * DIM + lane * 4);
        float4 e40 = h2f4(e0w), k40 = h2f4(k0w);
        float4 e41 = h2f4(e1w), k41 = h2f4(k1w);
        float d0 = q.x * (k40.x + e40.x) + q.y * (k40.y + e40.y) +
                   q.z * (k40.z + e40.z) + q.w * (k40.w + e40.w);
        float d1 = q.x * (k41.x + e41.x) + q.y * (k41.y + e41.y) +
                   q.z * (k41.z + e41.z) + q.w * (k41.w + e41.w);
#pragma unroll
        for (int o = 16; o; o >>= 1) {
            d0 += __shfl_xor_sync(0xFFFFFFFFu, d0, o);
            d1 += __shfl_xor_sync(0xFFFFFFFFu, d1, o);
        }
        float l0 = d0 * INV_SQRT_D, l1 = d1 * INV_SQRT_D;
        float4 v40 = h2f4(v0w), v41 = h2f4(v1w);
        {
            float nm = fmaxf(mA, l0);
            float corr = __expf(mA - nm), p = __expf(l0 - nm);
            sA = sA * corr + p;
            aA.x = aA.x * corr + p * (v40.x + e40.x);
            aA.y = aA.y * corr + p * (v40.y + e40.y);
            aA.z = aA.z * corr + p * (v40.z + e40.z);
            aA.w = aA.w * corr + p * (v40.w + e40.w);
            mA = nm;
        }
        {
            float nm = fmaxf(mB, l1);
            float corr = __expf(mB - nm), p = __expf(l1 - nm);
            sB = sB * corr + p;
            aB.x = aB.x * corr + p * (v41.x + e41.x);
            aB.y = aB.y * corr + p * (v41.y + e41.y);
            aB.z = aB.z * corr + p * (v41.z + e41.z);
            aB.w = aB.w * corr + p * (v41.w + e41.w);
            mB = nm;
        }
    }
    if (i < end) {
        int s0 = g_srt[i];
        uint2 e0w = *(const uint2*)(g_eh + (size_t)i * DIM + lane * 4);
        uint2 k0w = *(const uint2*)(g_kh + (size_t)s0 * DIM + lane * 4);
        uint2 v0w = *(const uint2*)(g_vh + (size_t)s0 * DIM + lane * 4);
        float4 e40 = h2f4(e0w), k40 = h2f4(k0w);
        float d0 = q.x * (k40.x + e40.x) + q.y * (k40.y + e40.y) +
                   q.z * (k40.z + e40.z) + q.w * (k40.w + e40.w);
#pragma unroll
        for (int o = 16; o; o >>= 1) d0 += __shfl_xor_sync(0xFFFFFFFFu, d0, o);
        float l0 = d0 * INV_SQRT_D;
        float4 v40 = h2f4(v0w);
        float nm = fmaxf(mA, l0);
        float corr = __expf(mA - nm), p = __expf(l0 - nm);
        sA = sA * corr + p;
        aA.x = aA.x * corr + p * (v40.x + e40.x);
        aA.y = aA.y * corr + p * (v40.y + e40.y);
        aA.z = aA.z * corr + p * (v40.z + e40.z);
        aA.w = aA.w * corr + p * (v40.w + e40.w);
        mA = nm;
    }

    // merge chains (mA is always finite here)
    float m = fmaxf(mA, mB);
    float cA = __expf(mA - m), cB = __expf(mB - m);
    float s = sA * cA + sB * cB;
    float invs = 1.0f / s;
    float4 out;
    out.x = (aA.x * cA + aB.x * cB) * invs;
    out.y = (aA.y * cA + aB.y * cB) * invs;
    out.z = (aA.z * cA + aB.z * cB) * invs;
    out.w = (aA.w * cA + aB.w * cB) * invs;
    ((float4*)&g_phi[(size_t)n * DIM])[lane] = out;
}

// ---------------- launch ----------------
extern "C" void kernel_launch(void* const* d_in, const int* in_sizes, int n_in,
                              void* d_out, int out_size) {
    const float* x      = (const float*)d_in[0];
    const float* lu     = (const float*)d_in[1];
    const float* t      = (const float*)d_in[2];
    const float* msg    = (const float*)d_in[3];
    const void*  ei     = d_in[4];
    const float* enc_W  = (const float*)d_in[5];
    const float* enc_b  = (const float*)d_in[6];
    const float* te_w   = (const float*)d_in[7];
    const float* te_b   = (const float*)d_in[8];
    const float* Wq     = (const float*)d_in[9];
    const float* bq     = (const float*)d_in[10];
    const float* Wk     = (const float*)d_in[11];
    const float* bk     = (const float*)d_in[12];
    const float* Wv     = (const float*)d_in[13];
    const float* bv     = (const float*)d_in[14];
    const float* We     = (const float*)d_in[15];
    const float* be     = (const float*)d_in[16];
    const float* Wanti  = (const float*)d_in[17];
    const float* banti  = (const float*)d_in[18];

    float *h, *phi, *te;
    __half *qh, *kh, *vh, *eh;
    int *pos;
    char *wimg_enc, *wimg_e, *wimg_qkv, *wimg_a;
    cudaGetSymbolAddress((void**)&h, g_h);
    cudaGetSymbolAddress((void**)&phi, g_phi);
    cudaGetSymbolAddress((void**)&te, g_te);
    cudaGetSymbolAddress((void**)&qh, g_qh);
    cudaGetSymbolAddress((void**)&kh, g_kh);
    cudaGetSymbolAddress((void**)&vh, g_vh);
    cudaGetSymbolAddress((void**)&eh, g_eh);
    cudaGetSymbolAddress((void**)&pos, g_pos);
    cudaGetSymbolAddress((void**)&wimg_enc, g_wimg_enc);
    cudaGetSymbolAddress((void**)&wimg_e, g_wimg_e);
    cudaGetSymbolAddress((void**)&wimg_qkv, g_wimg_qkv);
    cudaGetSymbolAddress((void**)&wimg_a, g_wimg_a);

    cudaFuncSetAttribute(qkv_gemm, cudaFuncAttributeMaxDynamicSharedMemorySize, 65536);

    // ---- preprocessing ----
    zero_kernel<<<(N_NODESC + 255) / 256, 256>>>();
    detect_kernel<<<1, 256>>>((const int*)ei);
    pre_kernel<<<N_EDGESC / 8, 256>>>(ei, lu, t, te_w, te_b);
    int nb = (N_NODESC + 1023) / 1024;   // 49
    scan1<<<nb, 1024>>>();
    scan2<<<1, 32>>>(nb);
    scan3<<<nb, 1024>>>();
    fill_kernel<<<(N_EDGESC + 255) / 256, 256>>>();

    build_wimg<<<(128 * 4 * 64 + 255) / 256, 256>>>(enc_W, wimg_enc, 256, 4);
    build_wimg<<<(128 * 3 * 64 + 255) / 256, 256>>>(We, wimg_e, 160, 3);
    build_wimg<<<(128 * 2 * 64 + 255) / 256, 256>>>(Wq, wimg_qkv, 128, 2);
    build_wimg<<<(128 * 2 * 64 + 255) / 256, 256>>>(Wk, wimg_qkv + 65536, 128, 2);
    build_wimg<<<(128 * 2 * 64 + 255) / 256, 256>>>(Wv, wimg_qkv + 2 * 65536, 128, 2);
    build_wimg_A<<<(128 * 128 + 255) / 256, 256>>>(Wanti, wimg_a);

    // ---- one-time GEMMs ----
    int gb_n = (N_NODESC + 63) / 64;   // 782
    int gb_e = N_EDGESC / 64;          // 12500
    mma_gemm<0><<<gb_n, 256>>>(x, 256, 256, nullptr, 0, 256,
                               wimg_enc, 4, enc_b, h, nullptr, nullptr, N_NODESC);
    mma_gemm<1><<<gb_e, 256>>>(msg, 128, 128, te, 32, 160,
                               wimg_e, 3, be, eh, nullptr, pos, N_EDGESC);

    // ---- 3 message-passing iterations ----
    for (int it = 0; it < 3; it++) {
        qkv_gemm<<<gb_n, 256, 65536>>>(h, wimg_qkv, bq, bk, bv, qh, kh, vh, N_NODESC);
        node_pass<<<(N_NODESC + 7) / 8, 256>>>();
        mma_gemm<2><<<gb_n, 256>>>(h, 128, 128, nullptr, 0, 128,
                                   wimg_a, 2, banti, h, phi, nullptr, N_NODESC);
    }

    cudaMemcpyAsync(d_out, h, (size_t)N_NODESC * DIM * sizeof(float),
                    cudaMemcpyDeviceToDevice);
}